// round 8
// baseline (speedup 1.0000x reference)
#include <cuda_runtime.h>
#include <cstdint>

typedef unsigned long long ull_t;

// ---- packed f32x2 helpers ----
__device__ __forceinline__ void ffma2(ull_t &acc, ull_t a, ull_t b) {
    asm volatile("fma.rn.f32x2 %0, %1, %2, %0;" : "+l"(acc) : "l"(a), "l"(b));
}
__device__ __forceinline__ ull_t add2(ull_t a, ull_t b) {
    ull_t r; asm("add.rn.f32x2 %0, %1, %2;" : "=l"(r) : "l"(a), "l"(b)); return r;
}
__device__ __forceinline__ float hsum2(ull_t v) {
    float lo, hi; asm("mov.b64 {%0,%1}, %2;" : "=f"(lo), "=f"(hi) : "l"(v));
    return lo + hi;
}
__device__ __forceinline__ ull_t pack2(float lo, float hi) {
    ull_t r; asm("mov.b64 %0, {%1, %2};" : "=l"(r) : "f"(lo), "f"(hi)); return r;
}
__device__ __forceinline__ ull_t mul2(ull_t a, ull_t b) {
    ull_t r; asm("mul.rn.f32x2 %0, %1, %2;" : "=l"(r) : "l"(a), "l"(b)); return r;
}

__device__ __forceinline__ void cp_async16(uint32_t dst, const void* src, int src_sz) {
    asm volatile("cp.async.cg.shared.global [%0], [%1], 16, %2;"
                 :: "r"(dst), "l"(src), "r"(src_sz));
}
__device__ __forceinline__ void cp_commit() {
    asm volatile("cp.async.commit_group;");
}
__device__ __forceinline__ void cp_wait1() {
    asm volatile("cp.async.wait_group 1;" ::: "memory");
}
// per-batch barrier over 64 threads (2 warps) — measured faster than bar0-128
__device__ __forceinline__ void group_bar(int id) {
    asm volatile("bar.sync %0, 64;" :: "r"(id) : "memory");
}

// =====================================================================
// FUSED kernel: recurrence + inline x-projection.
// Block = 128 thr = 2 independent batches (64 thr each, own named barrier).
// Thread = channel j. Raw x staged in CH-step chunks via cp.async.
// During chunk c's steps, step tt computes xp (= alpha*(x·W_in[j]+biases))
// for row tt of chunk c+1 into xpbuf — independent work that issues in the
// per-step barrier/latency bubbles (BAR.SYNC is defer-blocking).
// =====================================================================
__global__ void __launch_bounds__(128, 1)
ctrnn_fused_kernel(const float* __restrict__ x,
                   const float* __restrict__ W_in,
                   const float* __restrict__ b_in,
                   const float* __restrict__ W_hh,
                   const float* __restrict__ b_hh,
                   float* __restrict__ out,
                   int B, int T)
{
    constexpr int H  = 64;
    constexpr int D  = 32;
    constexpr int CH = 32;   // timesteps per x-staging chunk

    const int tid = threadIdx.x;
    const int sb  = tid >> 6;        // batch slot (0/1)
    const int j   = tid & 63;        // channel
    const int barid = sb + 1;
    const int b   = blockIdx.x * 2 + sb;
    const bool active = (b < B);
    const int bc  = active ? b : (B - 1);

    __shared__ __align__(16) float hbuf[2][2][H];            // 1KB
    __shared__ __align__(16) float xbuf[2][2][CH * D];       // raw x, 16KB
    __shared__ __align__(16) float xpbuf[2][2][CH][H];       // xp, 32KB

    const float alpha = (float)(16.67 / 40.0);
    const float oma   = (float)(1.0 - 16.67 / 40.0);
    const ull_t alpha2 = pack2(alpha, alpha);

    // Wa = alpha * W_hh[j] packed
    ull_t wu[32];
    {
        const ulonglong2* wr = reinterpret_cast<const ulonglong2*>(W_hh + j * H);
#pragma unroll
        for (int m = 0; m < 16; m++) {
            ulonglong2 v = wr[m];
            wu[2 * m]     = mul2(v.x, alpha2);
            wu[2 * m + 1] = mul2(v.y, alpha2);
        }
    }
    // Wi = alpha * W_in[j] packed; ab = alpha*(b_in[j]+b_hh[j])
    ull_t iu[16];
    {
        const ulonglong2* wr = reinterpret_cast<const ulonglong2*>(W_in + j * D);
#pragma unroll
        for (int m = 0; m < 8; m++) {
            ulonglong2 v = wr[m];
            iu[2 * m]     = mul2(v.x, alpha2);
            iu[2 * m + 1] = mul2(v.y, alpha2);
        }
    }
    const float ab = alpha * (b_in[j] + b_hh[j]);

    hbuf[0][sb][j] = 0.0f;
    float hj = 0.0f;

    const int nchunk = (T + CH - 1) / CH;

    // raw-x chunk loader: CH*D*4 = 4KB = 256 x 16B units; 64 thr -> 4 each
    auto issue_chunk = [&](int c, int buf) {
        const float* src = x + ((size_t)bc * T + (size_t)c * CH) * D;
        const char* srcb = (const char*)src;
        uint32_t dstb = (uint32_t)__cvta_generic_to_shared(&xbuf[buf][sb][0]);
#pragma unroll
        for (int q = 0; q < 4; q++) {
            int off16 = j + 64 * q;          // 256 units per chunk
            int row   = off16 >> 3;          // 8 units (128B) per timestep row
            bool ok   = active && (c * CH + row) < T;
            const void* s = ok ? (const void*)(srcb + (size_t)off16 * 16)
                               : (const void*)x;
            cp_async16(dstb + off16 * 16, s, ok ? 16 : 0);
        }
        cp_commit();
    };

    // xp of one staged row: dot(alpha*W_in[j], xrow) + ab
    auto xp_row = [&](const float* xrow) -> float {
        const ulonglong2* xr = reinterpret_cast<const ulonglong2*>(xrow);
        ull_t c0 = 0ull, c1 = 0ull, c2 = 0ull, c3 = 0ull;
#pragma unroll
        for (int m = 0; m < 8; m++) {
            ulonglong2 v = xr[m];
            ffma2((m & 1) ? c1 : c0, iu[2 * m],     v.x);
            ffma2((m & 1) ? c3 : c2, iu[2 * m + 1], v.y);
        }
        return hsum2(add2(add2(c0, c1), add2(c2, c3))) + ab;
    };

    // prologue: stage chunks 0,1; compute xp of chunk 0 as a burst
    issue_chunk(0, 0);
    if (nchunk > 1) issue_chunk(1, 1); else cp_commit();
    cp_wait1();            // own chunk-0 copies landed
    group_bar(barid);      // all threads' chunk-0 copies visible
#pragma unroll 4
    for (int r = 0; r < CH; r++)
        xpbuf[0][sb][r][j] = xp_row(&xbuf[0][sb][r * D]);
    group_bar(barid);      // xpbuf[0] visible; xbuf[0] free to overwrite

    int cur = 0;
    const size_t outbase = (size_t)bc * T * H + j;

#define STEP_BODY(tt)                                                              \
    {                                                                              \
        const ulonglong2* hp = reinterpret_cast<const ulonglong2*>(hbuf[cur][sb]); \
        const float xps = xpbuf[xb][sb][(tt)][j];                                  \
        ull_t a0 = pack2(xps, 0.0f);                                               \
        ull_t a1 = 0ull, a2 = 0ull, a3 = 0ull;                                     \
        _Pragma("unroll")                                                          \
        for (int m = 0; m < 16; m++) {                                             \
            ulonglong2 hv = hp[m];                                                 \
            ffma2((m & 1) ? a1 : a0, wu[2 * m],     hv.x);                         \
            ffma2((m & 1) ? a3 : a2, wu[2 * m + 1], hv.y);                         \
        }                                                                          \
        float p = hsum2(add2(add2(a0, a1), add2(a2, a3)));                         \
        float hnew = fmaxf(fmaf(hj, oma, p), 0.0f);                                \
        hbuf[cur ^ 1][sb][j] = hnew;                                               \
        if (active) out[obase_c + (size_t)(tt) * H] = hnew;                        \
        /* bubble-filler: xp of row tt of NEXT chunk (x already staged) */         \
        xpbuf[xb ^ 1][sb][(tt)][j] = xp_row(&xbuf[xb ^ 1][sb][(tt) * D]);          \
        hj = hnew;                                                                 \
        cur ^= 1;                                                                  \
        group_bar(barid);                                                          \
    }

    for (int c = 0; c < nchunk; c++) {
        const int xb = c & 1;
        // stage chunk c+2 into xbuf[xb] (chunk c's x already consumed)
        if (c + 2 < nchunk) issue_chunk(c + 2, xb); else cp_commit();
        cp_wait1();            // own chunk c+1 copies landed
        group_bar(barid);      // all threads: xbuf[xb^1] (chunk c+1) visible

        const int tend = min(CH, T - c * CH);
        const size_t obase_c = outbase + (size_t)c * CH * H;

        if (tend == CH) {
#pragma unroll 4
            for (int tt = 0; tt < CH; tt++) STEP_BODY(tt)
        } else {
            for (int tt = 0; tt < tend; tt++) STEP_BODY(tt)
        }
    }
#undef STEP_BODY

    // h_last appended after outputs
    if (active) out[(size_t)B * T * H + (size_t)b * H + j] = hj;
}

extern "C" void kernel_launch(void* const* d_in, const int* in_sizes, int n_in,
                              void* d_out, int out_size)
{
    const float* x    = (const float*)d_in[0];
    // d_in[1] = seq_lengths: forward-dead (mask only gates gradients)
    const float* W_in = (const float*)d_in[2];
    const float* b_in = (const float*)d_in[3];
    const float* W_hh = (const float*)d_in[4];
    const float* b_hh = (const float*)d_in[5];
    float* out = (float*)d_out;

    const int B = in_sizes[1];
    const int H = in_sizes[5];
    const int D = in_sizes[2] / H;
    const long long T = (long long)in_sizes[0] / ((long long)B * D);

    const int grid = (B + 1) / 2;
    ctrnn_fused_kernel<<<grid, 128>>>(x, W_in, b_in, W_hh, b_hh, out, B, (int)T);
}

// round 9
// speedup vs baseline: 1.1968x; 1.1968x over previous
#include <cuda_runtime.h>
#include <cstdint>

typedef unsigned long long ull_t;

// ---- packed f32x2 helpers ----
__device__ __forceinline__ void ffma2(ull_t &acc, ull_t a, ull_t b) {
    asm volatile("fma.rn.f32x2 %0, %1, %2, %0;" : "+l"(acc) : "l"(a), "l"(b));
}
__device__ __forceinline__ ull_t add2(ull_t a, ull_t b) {
    ull_t r; asm("add.rn.f32x2 %0, %1, %2;" : "=l"(r) : "l"(a), "l"(b)); return r;
}
__device__ __forceinline__ float hsum2(ull_t v) {
    float lo, hi; asm("mov.b64 {%0,%1}, %2;" : "=f"(lo), "=f"(hi) : "l"(v));
    return lo + hi;
}
__device__ __forceinline__ ull_t pack2(float lo, float hi) {
    ull_t r; asm("mov.b64 %0, {%1, %2};" : "=l"(r) : "f"(lo), "f"(hi)); return r;
}
__device__ __forceinline__ ull_t mul2(ull_t a, ull_t b) {
    ull_t r; asm("mul.rn.f32x2 %0, %1, %2;" : "=l"(r) : "l"(a), "l"(b)); return r;
}

__device__ __forceinline__ void cp_async16(uint32_t dst, const void* src, int src_sz) {
    asm volatile("cp.async.cg.shared.global [%0], [%1], 16, %2;"
                 :: "r"(dst), "l"(src), "r"(src_sz));
}
__device__ __forceinline__ void cp_commit() {
    asm volatile("cp.async.commit_group;");
}
__device__ __forceinline__ void cp_wait1() {
    asm volatile("cp.async.wait_group 1;" ::: "memory");
}
__device__ __forceinline__ void named_bar(int id, int cnt) {
    asm volatile("bar.sync %0, %1;" :: "r"(id), "r"(cnt) : "memory");
}

// =====================================================================
// Warp-specialized fused kernel. Block = 256 thr, 2 batches:
//   warps 0-1: recurrence batch0   (SMSP 0,1)
//   warps 2-3: recurrence batch1   (SMSP 2,3)
//   warps 4-5: xp producer batch0  (SMSP 0,1)
//   warps 6-7: xp producer batch1  (SMSP 2,3)
// Each SMSP: one latency-bound rec warp (~28% issue) + one producer warp
// that fills the idle slots computing next chunk's xp into a smem ring.
// Barriers: step bar = (1+sb, 64 thr, rec only);
//           chunk rendezvous = (3+sb, 128 thr, rec+xp of batch sb).
// =====================================================================
__global__ void __launch_bounds__(256, 1)
ctrnn_ws_kernel(const float* __restrict__ x,
                const float* __restrict__ W_in,
                const float* __restrict__ b_in,
                const float* __restrict__ W_hh,
                const float* __restrict__ b_hh,
                float* __restrict__ out,
                int B, int T)
{
    constexpr int H  = 64;
    constexpr int D  = 32;
    constexpr int CH = 32;   // timesteps per chunk

    const int tid  = threadIdx.x;
    const int role = tid >> 7;         // 0 = recurrence, 1 = xp producer
    const int sb   = (tid >> 6) & 1;   // batch slot
    const int j    = tid & 63;         // channel
    const int b    = blockIdx.x * 2 + sb;
    const bool active = (b < B);
    const int bc   = active ? b : (B - 1);

    __shared__ __align__(16) float hbuf[2][2][H];          // 1KB
    __shared__ __align__(16) float xbuf[2][2][CH * D];     // raw x ring, 16KB
    __shared__ __align__(16) float xpbuf[2][2][CH][H];     // xp ring, 32KB

    const float alpha = (float)(16.67 / 40.0);
    const float oma   = (float)(1.0 - 16.67 / 40.0);
    const ull_t alpha2 = pack2(alpha, alpha);

    const int nchunk = (T + CH - 1) / CH;

    if (role == 1) {
        // ================= XP PRODUCER =================
        // Wi = alpha * W_in[j]; ab = alpha*(b_in[j]+b_hh[j])
        ull_t iu[16];
        {
            const ulonglong2* wr = reinterpret_cast<const ulonglong2*>(W_in + j * D);
#pragma unroll
            for (int m = 0; m < 8; m++) {
                ulonglong2 v = wr[m];
                iu[2 * m]     = mul2(v.x, alpha2);
                iu[2 * m + 1] = mul2(v.y, alpha2);
            }
        }
        const float ab = alpha * (b_in[j] + b_hh[j]);

        // stage raw x chunk c into xbuf[buf]: 4KB = 256 x 16B; 64 thr -> 4 each
        auto issue_chunk = [&](int c, int buf) {
            const float* src = x + ((size_t)bc * T + (size_t)c * CH) * D;
            const char* srcb = (const char*)src;
            uint32_t dstb = (uint32_t)__cvta_generic_to_shared(&xbuf[buf][sb][0]);
#pragma unroll
            for (int q = 0; q < 4; q++) {
                int off16 = j + 64 * q;
                int row   = off16 >> 3;          // 8 units (128B) per row
                bool ok   = active && (c * CH + row) < T;
                const void* s = ok ? (const void*)(srcb + (size_t)off16 * 16)
                                   : (const void*)x;
                cp_async16(dstb + off16 * 16, s, ok ? 16 : 0);
            }
            cp_commit();
        };

        // xp of chunk c (x in xbuf[c&1]) -> xpbuf[c&1]; thread owns channel j
        auto produce = [&](int c) {
            const int rb   = c & 1;
            const int tend = min(CH, T - c * CH);
            for (int r = 0; r < tend; r++) {
                const ulonglong2* xr =
                    reinterpret_cast<const ulonglong2*>(&xbuf[rb][sb][r * D]);
                ull_t c0 = 0ull, c1 = 0ull, c2 = 0ull, c3 = 0ull;
#pragma unroll
                for (int m = 0; m < 8; m++) {
                    ulonglong2 v = xr[m];
                    ffma2((m & 1) ? c1 : c0, iu[2 * m],     v.x);
                    ffma2((m & 1) ? c3 : c2, iu[2 * m + 1], v.y);
                }
                xpbuf[rb][sb][r][j] =
                    hsum2(add2(add2(c0, c1), add2(c2, c3))) + ab;
            }
        };

        // prologue: stage ch0, ch1; produce xp0
        issue_chunk(0, 0);
        if (nchunk > 1) issue_chunk(1, 1); else cp_commit();
        cp_wait1();                 // own ch0 copies done
        named_bar(5 + sb, 64);      // all producer threads' ch0 visible
        produce(0);
        named_bar(3 + sb, 128);     // rendezvous: xp0 ready for rec warps

        for (int c = 0; c < nchunk; c++) {
            if (c + 2 < nchunk) issue_chunk(c + 2, c & 1); else cp_commit();
            if (c + 1 < nchunk) {
                cp_wait1();             // ch(c+1) landed (newest = c+2 pending)
                named_bar(5 + sb, 64);  // group visibility of ch(c+1)
                produce(c + 1);         // fills rec's idle issue slots
            }
            named_bar(3 + sb, 128);     // end-of-chunk rendezvous with rec
        }
    } else {
        // ================= RECURRENCE (R4 hot loop, xp from smem ring) =====
        ull_t wu[32];
        {
            const ulonglong2* wr = reinterpret_cast<const ulonglong2*>(W_hh + j * H);
#pragma unroll
            for (int m = 0; m < 16; m++) {
                ulonglong2 v = wr[m];
                wu[2 * m]     = mul2(v.x, alpha2);
                wu[2 * m + 1] = mul2(v.y, alpha2);
            }
        }

        hbuf[0][sb][j] = 0.0f;
        float hj = 0.0f;

        int cur = 0;
        const size_t outbase = (size_t)bc * T * H + j;

        named_bar(3 + sb, 128);     // wait for xp chunk 0

        for (int c = 0; c < nchunk; c++) {
            const int xb   = c & 1;
            const int tend = min(CH, T - c * CH);
            const size_t obase_c = outbase + (size_t)c * CH * H;

#define STEP_BODY(tt)                                                              \
    {                                                                              \
        const ulonglong2* hp = reinterpret_cast<const ulonglong2*>(hbuf[cur][sb]); \
        const float xps = xpbuf[xb][sb][(tt)][j];                                  \
        ull_t a0 = pack2(xps, 0.0f);                                               \
        ull_t a1 = 0ull, a2 = 0ull, a3 = 0ull;                                     \
        _Pragma("unroll")                                                          \
        for (int m = 0; m < 16; m++) {                                             \
            ulonglong2 hv = hp[m];                                                 \
            ffma2((m & 1) ? a1 : a0, wu[2 * m],     hv.x);                         \
            ffma2((m & 1) ? a3 : a2, wu[2 * m + 1], hv.y);                         \
        }                                                                          \
        float p = hsum2(add2(add2(a0, a1), add2(a2, a3)));                         \
        float hnew = fmaxf(fmaf(hj, oma, p), 0.0f);                                \
        hbuf[cur ^ 1][sb][j] = hnew;                                               \
        if (active) out[obase_c + (size_t)(tt) * H] = hnew;                        \
        hj = hnew;                                                                 \
        cur ^= 1;                                                                  \
        named_bar(1 + sb, 64);                                                     \
    }

            if (tend == CH) {
#pragma unroll 4
                for (int tt = 0; tt < CH; tt++) STEP_BODY(tt)
            } else {
                for (int tt = 0; tt < tend; tt++) STEP_BODY(tt)
            }
#undef STEP_BODY

            named_bar(3 + sb, 128);   // chunk done; next xp ring slot ready
        }

        // h_last appended after outputs
        if (active) out[(size_t)B * T * H + (size_t)b * H + j] = hj;
    }
}

extern "C" void kernel_launch(void* const* d_in, const int* in_sizes, int n_in,
                              void* d_out, int out_size)
{
    const float* x    = (const float*)d_in[0];
    // d_in[1] = seq_lengths: forward-dead (mask only gates gradients)
    const float* W_in = (const float*)d_in[2];
    const float* b_in = (const float*)d_in[3];
    const float* W_hh = (const float*)d_in[4];
    const float* b_hh = (const float*)d_in[5];
    float* out = (float*)d_out;

    const int B = in_sizes[1];
    const int H = in_sizes[5];
    const int D = in_sizes[2] / H;
    const long long T = (long long)in_sizes[0] / ((long long)B * D);

    const int grid = (B + 1) / 2;
    ctrnn_ws_kernel<<<grid, 256>>>(x, W_in, b_in, W_hh, b_hh, out, B, (int)T);
}